// round 7
// baseline (speedup 1.0000x reference)
#include <cuda_runtime.h>
#include <cstdint>

#define IMG_H 512
#define IMG_W 512
#define TILE_R 8
#define STAGES 3
#define TILES_PER_BLOCK 8                      // band = 64 rows
#define BAND_ROWS (TILE_R * TILES_PER_BLOCK)   // 64
#define XROWS (TILE_R + 2)                     // 10 (with top/bottom halo)
#define ROW_FLOATS IMG_W
#define ROW_BYTES (IMG_W * 4)                  // 2048
#define X_STAGE_FLOATS (XROWS * ROW_FLOATS)
#define F_STAGE_FLOATS (TILE_R * ROW_FLOATS)
#define STAGE_FLOATS (X_STAGE_FLOATS + F_STAGE_FLOATS)
#define SMEM_BYTES (STAGES * STAGE_FLOATS * 4) // 110592

__device__ __forceinline__ uint32_t smem_u32(const void* p) {
    uint32_t a;
    asm("{ .reg .u64 t; cvta.to.shared.u64 t, %1; cvt.u32.u64 %0, t; }"
        : "=r"(a) : "l"(p));
    return a;
}

__device__ __forceinline__ void mbar_init(uint32_t addr, uint32_t count) {
    asm volatile("mbarrier.init.shared.b64 [%0], %1;" :: "r"(addr), "r"(count) : "memory");
}
__device__ __forceinline__ void mbar_arrive(uint32_t addr) {
    asm volatile("mbarrier.arrive.shared.b64 _, [%0];" :: "r"(addr) : "memory");
}
__device__ __forceinline__ void mbar_expect_tx(uint32_t addr, uint32_t tx) {
    asm volatile("mbarrier.arrive.expect_tx.shared.b64 _, [%0], %1;"
                 :: "r"(addr), "r"(tx) : "memory");
}
__device__ __forceinline__ void mbar_wait(uint32_t addr, uint32_t phase) {
    asm volatile(
        "{\n\t.reg .pred P;\n\t"
        "LW_%=:\n\t"
        "mbarrier.try_wait.parity.acquire.cta.shared::cta.b64 P, [%0], %1, 0x989680;\n\t"
        "@P bra.uni LD_%=;\n\t"
        "bra.uni LW_%=;\n\t"
        "LD_%=:\n\t}"
        :: "r"(addr), "r"(phase) : "memory");
}
__device__ __forceinline__ void bulk_copy_g2s(uint32_t dst, const void* src,
                                              uint32_t bytes, uint32_t mbar) {
    asm volatile(
        "cp.async.bulk.shared::cluster.global.mbarrier::complete_tx::bytes "
        "[%0], [%1], %2, [%3];"
        :: "r"(dst), "l"(src), "r"(bytes), "r"(mbar) : "memory");
}

__global__ __launch_bounds__(256, 2)
void cheby_smooth_kernel(const float* __restrict__ x,
                         const float* __restrict__ f,
                         const float* __restrict__ kA,
                         float* __restrict__ out)
{
    extern __shared__ __align__(16) float smem[];
    __shared__ __align__(8) unsigned long long mbar_store[2 * STAGES];

    const int tid  = threadIdx.x;
    const int lane = tid & 31;
    const int w    = tid >> 5;                   // 0..7 (warp id == row within tile)
    const int b    = blockIdx.y;                 // image index
    const int band0 = blockIdx.x * BAND_ROWS;    // first output row of this band

    const uint32_t mb = smem_u32(mbar_store);    // full[s] at mb+8s, empty[s] at mb+8(STAGES+s)

    const size_t base = (size_t)b * IMG_H * IMG_W;
    const float* __restrict__ xb = x + base;
    const float* __restrict__ fb = f + base;
    float* __restrict__ ob = out + base;

    // 3x3 kernel: warp-uniform scalar loads (broadcast), once per block.
    float kk[9];
    #pragma unroll
    for (int i = 0; i < 9; ++i) kk[i] = kA[b * 9 + i];

    if (tid == 0) {
        #pragma unroll
        for (int s = 0; s < STAGES; ++s) {
            mbar_init(mb + 8u * s, 1);                 // full: 1 expect_tx arrive + tx bytes
            mbar_init(mb + 8u * (STAGES + s), 256);    // empty: all threads arrive
        }
    }
    __syncthreads();

    // ---- producer: issue bulk copies for tile t into its ring slot ----
    auto issue_tile = [&](int t) {
        const int r0  = band0 + t * TILE_R;
        const int buf = t % STAGES;
        float* xs = smem + (size_t)buf * STAGE_FLOATS;
        float* fs = xs + X_STAGE_FLOATS;
        int g0 = r0 - 1, g1 = r0 + TILE_R + 1;
        if (g0 < 0) g0 = 0;
        if (g1 > IMG_H) g1 = IMG_H;
        const uint32_t xbytes  = (uint32_t)(g1 - g0) * ROW_BYTES;
        const uint32_t dst_off = (uint32_t)(g0 - (r0 - 1)) * ROW_BYTES;
        const uint32_t mfull = mb + 8u * buf;
        mbar_expect_tx(mfull, xbytes + (uint32_t)(TILE_R * ROW_BYTES));
        bulk_copy_g2s(smem_u32(xs) + dst_off, xb + (size_t)g0 * IMG_W, xbytes, mfull);
        bulk_copy_g2s(smem_u32(fs), fb + (size_t)r0 * IMG_W, TILE_R * ROW_BYTES, mfull);
    };

    if (tid == 0) {
        #pragma unroll
        for (int s = 0; s < STAGES; ++s) issue_tile(s);
    }

    const float inv6 = 1.0f / 6.0f;
    const int c0 = lane * 16;                    // this lane's 16 contiguous columns

    for (int t = 0; t < TILES_PER_BLOCK; ++t) {
        const int buf = t % STAGES;
        const int ph  = (t / STAGES) & 1;
        const int r0  = band0 + t * TILE_R;
        const int g   = r0 + w;                  // this warp's output row

        mbar_wait(mb + 8u * buf, (uint32_t)ph);

        const float* xs = smem + (size_t)buf * STAGE_FLOATS;
        const float* fs = xs + X_STAGE_FLOATS;

        float a[16];
        #pragma unroll
        for (int c = 0; c < 16; ++c) a[c] = 0.f;
        float xc[16];

        #pragma unroll
        for (int tt = 0; tt < 3; ++tt) {
            const int gr   = g - 1 + tt;
            const bool vr  = (gr >= 0) && (gr < IMG_H);
            const float* s = xs + (size_t)(w + tt) * ROW_FLOATS + c0;

            float v[18];
            float4 m;
            #pragma unroll
            for (int q = 0; q < 4; ++q) {
                m = *reinterpret_cast<const float4*>(s + 4 * q);
                v[1 + 4*q + 0] = vr ? m.x : 0.f;
                v[1 + 4*q + 1] = vr ? m.y : 0.f;
                v[1 + 4*q + 2] = vr ? m.z : 0.f;
                v[1 + 4*q + 3] = vr ? m.w : 0.f;
            }
            const float l = __shfl_up_sync(0xffffffffu, v[16], 1);
            const float r = __shfl_down_sync(0xffffffffu, v[1], 1);
            v[0]  = (lane == 0)  ? 0.f : l;      // image-left edge (blocks span full width)
            v[17] = (lane == 31) ? 0.f : r;      // image-right edge

            const float k0 = kk[tt * 3 + 0];
            const float k1 = kk[tt * 3 + 1];
            const float k2 = kk[tt * 3 + 2];
            #pragma unroll
            for (int c = 0; c < 16; ++c)
                a[c] = fmaf(v[c], k0, fmaf(v[c + 1], k1, fmaf(v[c + 2], k2, a[c])));

            if (tt == 1) {
                #pragma unroll
                for (int c = 0; c < 16; ++c) xc[c] = v[c + 1];
            }
        }

        // f row + epilogue + store (4 x STG.128)
        const float* fr = fs + (size_t)w * ROW_FLOATS + c0;
        float* orow = ob + (size_t)g * IMG_W + c0;
        #pragma unroll
        for (int q = 0; q < 4; ++q) {
            const float4 fv = *reinterpret_cast<const float4*>(fr + 4 * q);
            float4 o;
            o.x = xc[4*q + 0] + (fv.x - a[4*q + 0]) * inv6;
            o.y = xc[4*q + 1] + (fv.y - a[4*q + 1]) * inv6;
            o.z = xc[4*q + 2] + (fv.z - a[4*q + 2]) * inv6;
            o.w = xc[4*q + 3] + (fv.w - a[4*q + 3]) * inv6;
            *reinterpret_cast<float4*>(orow + 4 * q) = o;
        }

        // Done reading this slot.
        mbar_arrive(mb + 8u * (STAGES + buf));

        // Refill the slot for tile t+STAGES once everyone has consumed it.
        const int tn = t + STAGES;
        if (tn < TILES_PER_BLOCK && tid == 0) {
            const uint32_t rph = (uint32_t)(((tn / STAGES) - 1) & 1);
            mbar_wait(mb + 8u * (STAGES + buf), rph);
            issue_tile(tn);
        }
    }
}

extern "C" void kernel_launch(void* const* d_in, const int* in_sizes, int n_in,
                              void* d_out, int out_size)
{
    const float* x  = (const float*)d_in[0];   // [64,1,512,512]
    const float* f  = (const float*)d_in[1];   // [64,1,512,512]
    const float* kA = (const float*)d_in[2];   // [64,1,3,3]
    float* out = (float*)d_out;

    static int smem_set = 0;
    if (!smem_set) {
        cudaFuncSetAttribute(cheby_smooth_kernel,
                             cudaFuncAttributeMaxDynamicSharedMemorySize, SMEM_BYTES);
        smem_set = 1;
    }

    dim3 block(256, 1, 1);
    dim3 grid(IMG_H / BAND_ROWS, 64, 1);   // (8 bands, 64 images)
    cheby_smooth_kernel<<<grid, block, SMEM_BYTES>>>(x, f, kA, out);
}

// round 8
// speedup vs baseline: 1.7425x; 1.7425x over previous
#include <cuda_runtime.h>

#define IMG_H 512
#define IMG_W 512

__global__ __launch_bounds__(128)
void cheby_smooth_kernel(const float* __restrict__ x,
                         const float* __restrict__ f,
                         const float* __restrict__ kA,
                         float* __restrict__ out)
{
    const int b    = blockIdx.z;
    const int lane = threadIdx.x;                                 // blockDim.x == 32
    const int r0   = (blockIdx.y * 4 + threadIdx.y) * 8;          // first of 8 output rows
    const int c0   = (blockIdx.x * 32 + lane) * 4;                // first of 4 output cols

    // Stage this batch's 3x3 kernel into smem (one broadcast load per block).
    __shared__ float k[9];
    if (threadIdx.y == 0 && lane < 9)
        k[lane] = kA[b * 9 + lane];
    __syncthreads();

    const size_t base = (size_t)b * IMG_H * IMG_W;
    const float* __restrict__ xb = x + base;
    const float* __restrict__ fb = f + base;
    float* __restrict__ ob = out + base;

    // ---- Phase 1: issue ALL global loads up front (max MLP), streaming policy ----
    float4 mid[10];
    float  lf[10], rt[10];

    #pragma unroll
    for (int i = 0; i < 10; ++i) {
        const int rr = r0 - 1 + i;
        const bool valid = (rr >= 0) && (rr < IMG_H);
        const float* __restrict__ row = xb + (size_t)rr * IMG_W;
        mid[i] = valid ? __ldcs(reinterpret_cast<const float4*>(row + c0))
                       : make_float4(0.f, 0.f, 0.f, 0.f);
        // Only lanes 0 / 31 need a real boundary element (predicated scalar LDG).
        lf[i] = (lane == 0  && valid && c0 > 0)         ? __ldcs(row + c0 - 1) : 0.f;
        rt[i] = (lane == 31 && valid && c0 + 4 < IMG_W) ? __ldcs(row + c0 + 4) : 0.f;
    }

    float4 fv[8];
    #pragma unroll
    for (int j = 0; j < 8; ++j)
        fv[j] = __ldcs(reinterpret_cast<const float4*>(fb + (size_t)(r0 + j) * IMG_W + c0));

    // ---- Phase 2: intra-warp halo exchange ----
    #pragma unroll
    for (int i = 0; i < 10; ++i) {
        const float l = __shfl_up_sync(0xffffffffu, mid[i].w, 1);
        const float r = __shfl_down_sync(0xffffffffu, mid[i].x, 1);
        if (lane != 0)  lf[i] = l;
        if (lane != 31) rt[i] = r;
    }

    // ---- Phase 3: compute 8 output rows ----
    const float inv6 = 1.0f / 6.0f;

    #pragma unroll
    for (int j = 0; j < 8; ++j) {
        float a0 = 0.f, a1 = 0.f, a2 = 0.f, a3 = 0.f;
        #pragma unroll
        for (int t = 0; t < 3; ++t) {
            const int i = j + t;
            const float k0 = k[t * 3 + 0];
            const float k1 = k[t * 3 + 1];
            const float k2 = k[t * 3 + 2];
            a0 = fmaf(lf[i],    k0, fmaf(mid[i].x, k1, fmaf(mid[i].y, k2, a0)));
            a1 = fmaf(mid[i].x, k0, fmaf(mid[i].y, k1, fmaf(mid[i].z, k2, a1)));
            a2 = fmaf(mid[i].y, k0, fmaf(mid[i].z, k1, fmaf(mid[i].w, k2, a2)));
            a3 = fmaf(mid[i].z, k0, fmaf(mid[i].w, k1, fmaf(rt[i],    k2, a3)));
        }
        const float4 xc = mid[j + 1];
        float4 o;
        o.x = xc.x + (fv[j].x - a0) * inv6;
        o.y = xc.y + (fv[j].y - a1) * inv6;
        o.z = xc.z + (fv[j].z - a2) * inv6;
        o.w = xc.w + (fv[j].w - a3) * inv6;
        __stcs(reinterpret_cast<float4*>(ob + (size_t)(r0 + j) * IMG_W + c0), o);
    }
}

extern "C" void kernel_launch(void* const* d_in, const int* in_sizes, int n_in,
                              void* d_out, int out_size)
{
    const float* x  = (const float*)d_in[0];   // [64,1,512,512]
    const float* f  = (const float*)d_in[1];   // [64,1,512,512]
    const float* kA = (const float*)d_in[2];   // [64,1,3,3]
    float* out = (float*)d_out;

    dim3 block(32, 4, 1);
    dim3 grid(IMG_W / (32 * 4), IMG_H / (4 * 8), 64); // (4, 16, 64)
    cheby_smooth_kernel<<<grid, block>>>(x, f, kA, out);
}